// round 1
// baseline (speedup 1.0000x reference)
#include <cuda_runtime.h>

// Problem constants
#define BB 16
#define CC 512
#define GG 32
#define TT 180
#define NN 1024   // H*W
#define FF 1024
#define SCALE 0.04419417382415922f  // 512^-0.5
#define EPSF 1e-6f

// ---------------- scratch (no allocs allowed) ----------------
__device__ __align__(16) float g_part[32 * 512];      // partial column sums of wq
__device__ __align__(16) float g_wa[512];             // wqs[c]*gamma[c]
__device__ __align__(16) float g_wg[32];              // per-group sum of wa
__device__ __align__(16) float g_Wsum[512];           // row sums of wo
__device__ float g_const1;                            // sum(wqs*beta) + sum(bq)
__device__ __align__(16) float g_P[BB * GG * NN];     // 2MB partial channel sums
__device__ float g_sum[BB * GG];
__device__ float g_sq[BB * GG];
__device__ float g_rs[BB * GG];
__device__ float g_d[BB];
__device__ __align__(16) float g_k[BB * FF];
__device__ __align__(16) float g_v[BB * FF];
__device__ __align__(16) float g_A[BB * NN];

// ---------------- K1a: weight partial reductions ----------------
// grid 32, block 512. Block j reduces 16 rows of wq into column partials,
// and computes 16 full row-sums of wo (one warp per row).
__global__ void k1a(const float* __restrict__ wq, const float* __restrict__ wo) {
    int j = blockIdx.x;
    int c = threadIdx.x;
    float s = 0.f;
#pragma unroll
    for (int o = 0; o < 16; o++) s += wq[(j * 16 + o) * 512 + c];
    g_part[j * 512 + c] = s;

    int w = threadIdx.x >> 5, lane = threadIdx.x & 31;
    const float* row = wo + (j * 16 + w) * 512;
    float r = 0.f;
    for (int t = lane; t < 512; t += 32) r += row[t];
#pragma unroll
    for (int off = 16; off; off >>= 1) r += __shfl_down_sync(0xffffffffu, r, off);
    if (lane == 0) g_Wsum[j * 16 + w] = r;
}

// ---------------- K1b: finalize weight reductions ----------------
// 1 block, 512 threads.
__global__ void k1b(const float* __restrict__ gamma, const float* __restrict__ beta,
                    const float* __restrict__ bq) {
    int c = threadIdx.x;
    float wqs = 0.f;
#pragma unroll 8
    for (int j = 0; j < 32; j++) wqs += g_part[j * 512 + c];
    float wa = wqs * gamma[c];
    g_wa[c] = wa;

    // const term: sum(wqs*beta) + sum(bq)
    __shared__ float sm[512];
    sm[c] = wqs * beta[c] + bq[c];
    __syncthreads();
    for (int st = 256; st; st >>= 1) {
        if (c < st) sm[c] += sm[c + st];
        __syncthreads();
    }
    if (c == 0) g_const1 = sm[0];

    // per-group sum of wa (groups of 16 consecutive channels)
    float wgv = wa;
#pragma unroll
    for (int off = 8; off; off >>= 1) wgv += __shfl_down_sync(0xffffffffu, wgv, off, 16);
    if ((c & 15) == 0) g_wg[c >> 4] = wgv;
}

// ---------------- K2: fused group stats + weighted channel partials ----------------
// grid 512 (one per (b,g)), block 256. Reads x once (float4).
__global__ void k2(const float* __restrict__ x) {
    int bg = blockIdx.x;
    int g = bg & 31;
    const float4* xs = (const float4*)x + (size_t)bg * 16 * 256;  // (b*32+g)*16 chans * 256 f4
    int t = threadIdx.x;

    float4 p = make_float4(0.f, 0.f, 0.f, 0.f);
    float sum = 0.f, sq = 0.f;
#pragma unroll
    for (int c = 0; c < 16; c++) {
        float w = g_wa[g * 16 + c];
        float4 v = xs[c * 256 + t];
        sum += v.x + v.y + v.z + v.w;
        sq += v.x * v.x + v.y * v.y + v.z * v.z + v.w * v.w;
        p.x += w * v.x; p.y += w * v.y; p.z += w * v.z; p.w += w * v.w;
    }
    ((float4*)g_P)[bg * 256 + t] = p;

    __shared__ float s1[256], s2[256];
    s1[t] = sum; s2[t] = sq;
    __syncthreads();
    for (int st = 128; st; st >>= 1) {
        if (t < st) { s1[t] += s1[t + st]; s2[t] += s2[t + st]; }
        __syncthreads();
    }
    if (t == 0) { g_sum[bg] = s1[0]; g_sq[bg] = s2[0]; }
}

// ---------------- K3: k/v tiny GEMM: [16,1024] = cond[16,180] @ W^T ----------------
// grid (8 f-chunks, 2 mats, 2 b-halves), block 128.
__global__ void k3_kv(const float* __restrict__ cond,
                      const float* __restrict__ wk, const float* __restrict__ bk,
                      const float* __restrict__ wv, const float* __restrict__ bv) {
    const float* W = blockIdx.y ? wv : wk;
    const float* bias = blockIdx.y ? bv : bk;
    float* out = blockIdx.y ? g_v : g_k;
    int b0 = blockIdx.z * 8;

    __shared__ float4 sc[8][45];
    for (int i = threadIdx.x; i < 8 * 45; i += 128) {
        int bb = i / 45, ii = i % 45;
        sc[bb][ii] = ((const float4*)(cond + (b0 + bb) * TT))[ii];
    }
    __syncthreads();

    int f = blockIdx.x * 128 + threadIdx.x;
    const float4* wrow = (const float4*)(W + (size_t)f * TT);
    float acc[8] = {0.f, 0.f, 0.f, 0.f, 0.f, 0.f, 0.f, 0.f};
#pragma unroll 5
    for (int i = 0; i < 45; i++) {
        float4 w4 = wrow[i];
#pragma unroll
        for (int bb = 0; bb < 8; bb++) {
            float4 c4 = sc[bb][i];
            acc[bb] += w4.x * c4.x + w4.y * c4.y + w4.z * c4.z + w4.w * c4.w;
        }
    }
    float bf = bias[f];
#pragma unroll
    for (int bb = 0; bb < 8; bb++) out[(b0 + bb) * FF + f] = acc[bb] + bf;
}

// ---------------- K4: finalize stats -> rs, per-batch offset d ----------------
// 1 block, 512 threads. warp w == batch b; lane == group g.
__global__ void k4() {
    int t = threadIdx.x;
    const float inv = 1.f / 16384.f;
    float mean = g_sum[t] * inv;
    float var = g_sq[t] * inv - mean * mean;
    float rs = rsqrtf(var + EPSF);
    g_rs[t] = rs;
    float contrib = mean * rs * g_wg[t & 31];
#pragma unroll
    for (int off = 16; off; off >>= 1)
        contrib += __shfl_down_sync(0xffffffffu, contrib, off);
    if ((t & 31) == 0) g_d[t >> 5] = g_const1 - contrib;
}

// ---------------- K5: S + softmax-weighted-average -> A[b,n] ----------------
// grid (128, 16), block 256 (8 warps; warp = one n).
// Logits are tiny (|l| < ~3 by construction: 0.02-scaled weights), so we skip
// the max-subtraction: exp never overflows and the ratio is exact.
__global__ void k5() {
    __shared__ float4 sk[256], sv[256];
    int b = blockIdx.y;
    int tid = threadIdx.x;
    sk[tid] = ((const float4*)(g_k + b * FF))[tid];
    sv[tid] = ((const float4*)(g_v + b * FF))[tid];
    __syncthreads();

    int w = tid >> 5, lane = tid & 31;
    int n = blockIdx.x * 8 + w;

    // S[b,n] = sum_g rs[b,g] * P[b,g,n] + d[b]   (lane-per-group)
    float ps = g_rs[b * 32 + lane] * g_P[((size_t)b * 32 + lane) * NN + n];
#pragma unroll
    for (int off = 16; off; off >>= 1) ps += __shfl_xor_sync(0xffffffffu, ps, off);
    float s = (ps + g_d[b]) * SCALE;

    float l = 0.f, acc = 0.f;
#pragma unroll
    for (int j = 0; j < 8; j++) {
        float4 k4v = sk[j * 32 + lane];
        float4 v4 = sv[j * 32 + lane];
        float e0 = __expf(s * k4v.x), e1 = __expf(s * k4v.y);
        float e2 = __expf(s * k4v.z), e3 = __expf(s * k4v.w);
        l += e0 + e1 + e2 + e3;
        acc += v4.x * e0 + v4.y * e1 + v4.z * e2 + v4.w * e3;
    }
#pragma unroll
    for (int off = 16; off; off >>= 1) {
        l += __shfl_xor_sync(0xffffffffu, l, off);
        acc += __shfl_xor_sync(0xffffffffu, acc, off);
    }
    if (lane == 0) g_A[b * NN + n] = acc / l;
}

// ---------------- K6: out = x + Wsum[c]*A[b,n] + bo[c] ----------------
// float4 over n. 8192 blocks x 256.
__global__ void k6(const float* __restrict__ x, const float* __restrict__ bo,
                   float* __restrict__ out) {
    size_t i = (size_t)blockIdx.x * 256 + threadIdx.x;  // float4 index
    int n4 = (int)(i & 255);
    int c = (int)((i >> 8) & 511);
    int b = (int)(i >> 17);
    float4 xv = ((const float4*)x)[i];
    float4 av = ((const float4*)g_A)[b * 256 + n4];
    float wv = g_Wsum[c];
    float bb = bo[c];
    float4 o;
    o.x = xv.x + wv * av.x + bb;
    o.y = xv.y + wv * av.y + bb;
    o.z = xv.z + wv * av.z + bb;
    o.w = xv.w + wv * av.w + bb;
    ((float4*)out)[i] = o;
}

extern "C" void kernel_launch(void* const* d_in, const int* in_sizes, int n_in,
                              void* d_out, int out_size) {
    const float* x     = (const float*)d_in[0];
    const float* cond  = (const float*)d_in[1];
    const float* gamma = (const float*)d_in[2];
    const float* beta  = (const float*)d_in[3];
    const float* wq    = (const float*)d_in[4];
    const float* bq    = (const float*)d_in[5];
    const float* wk    = (const float*)d_in[6];
    const float* bk    = (const float*)d_in[7];
    const float* wv    = (const float*)d_in[8];
    const float* bv    = (const float*)d_in[9];
    const float* wo    = (const float*)d_in[10];
    const float* bo    = (const float*)d_in[11];
    float* out = (float*)d_out;

    k1a<<<32, 512>>>(wq, wo);
    k1b<<<1, 512>>>(gamma, beta, bq);
    k2<<<512, 256>>>(x);
    k3_kv<<<dim3(8, 2, 2), 128>>>(cond, wk, bk, wv, bv);
    k4<<<1, 512>>>();
    k5<<<dim3(128, 16), 256>>>();
    k6<<<8192, 256>>>(x, bo, out);
}

// round 2
// speedup vs baseline: 1.3531x; 1.3531x over previous
#include <cuda_runtime.h>

// Problem constants
#define BB 16
#define CC 512
#define GG 32
#define TT 180
#define NN 1024   // H*W
#define FF 1024
#define SCALE 0.04419417382415922f  // 512^-0.5
#define EPSF 1e-6f

// ---------------- scratch (no allocs allowed) ----------------
__device__ __align__(16) float g_part[32 * 512];      // partial column sums of wq
__device__ __align__(16) float g_wa[512];             // wqs[c]*gamma[c]
__device__ __align__(16) float g_wg[32];              // per-group sum of wa
__device__ __align__(16) float g_Wsum[512];           // row sums of wo
__device__ float g_const1;                            // sum(wqs*beta) + sum(bq)
__device__ __align__(16) float g_P[BB * GG * NN];     // 2MB partial channel sums
__device__ float g_sum[BB * GG];
__device__ float g_sq[BB * GG];
__device__ float g_rs[BB * GG];
__device__ float g_d[BB];
__device__ __align__(16) float g_k[BB * FF];
__device__ __align__(16) float g_v[BB * FF];
__device__ __align__(16) float g_A[BB * NN];

// ---------------- K1a: weight partial reductions ----------------
// grid 32, block 512. Block j reduces 16 rows of wq into column partials,
// and computes 16 full row-sums of wo (one warp per row).
__global__ void k1a(const float* __restrict__ wq, const float* __restrict__ wo) {
    int j = blockIdx.x;
    int c = threadIdx.x;
    float s = 0.f;
#pragma unroll
    for (int o = 0; o < 16; o++) s += wq[(j * 16 + o) * 512 + c];
    g_part[j * 512 + c] = s;

    int w = threadIdx.x >> 5, lane = threadIdx.x & 31;
    const float* row = wo + (j * 16 + w) * 512;
    float r = 0.f;
    for (int t = lane; t < 512; t += 32) r += row[t];
#pragma unroll
    for (int off = 16; off; off >>= 1) r += __shfl_down_sync(0xffffffffu, r, off);
    if (lane == 0) g_Wsum[j * 16 + w] = r;
}

// ---------------- K1b: finalize weight reductions ----------------
// 1 block, 512 threads.
__global__ void k1b(const float* __restrict__ gamma, const float* __restrict__ beta,
                    const float* __restrict__ bq) {
    int c = threadIdx.x;
    float wqs = 0.f;
#pragma unroll 8
    for (int j = 0; j < 32; j++) wqs += g_part[j * 512 + c];
    float wa = wqs * gamma[c];
    g_wa[c] = wa;

    // const term: sum(wqs*beta) + sum(bq)
    __shared__ float sm[512];
    sm[c] = wqs * beta[c] + bq[c];
    __syncthreads();
    for (int st = 256; st; st >>= 1) {
        if (c < st) sm[c] += sm[c + st];
        __syncthreads();
    }
    if (c == 0) g_const1 = sm[0];

    // per-group sum of wa (groups of 16 consecutive channels)
    float wgv = wa;
#pragma unroll
    for (int off = 8; off; off >>= 1) wgv += __shfl_down_sync(0xffffffffu, wgv, off, 16);
    if ((c & 15) == 0) g_wg[c >> 4] = wgv;
}

// ---------------- K23: fused  (k2: group stats + weighted partials)  ∪  (k3: k/v GEMM) ----
// grid 640, block 256.
//   blocks [0,512): k2 — one block per (b,g), reads x once (float4).
//   blocks [512,640): k3 — tiled smem GEMM, 16f x 16b outputs per block.
// k3's compute hides fully under k2's DRAM stream.
__global__ void k23(const float* __restrict__ x, const float* __restrict__ cond,
                    const float* __restrict__ wk, const float* __restrict__ bk,
                    const float* __restrict__ wv, const float* __restrict__ bv) {
    __shared__ float smem[2 * 16 * 181];   // 23.2KB; k2 aliases the front 2KB
    int t = threadIdx.x;

    if (blockIdx.x < 512) {
        // ---- k2 body ----
        int bg = blockIdx.x;
        int g = bg & 31;
        const float4* xs = (const float4*)x + (size_t)bg * 16 * 256;

        float4 p = make_float4(0.f, 0.f, 0.f, 0.f);
        float sum = 0.f, sq = 0.f;
#pragma unroll
        for (int c = 0; c < 16; c++) {
            float w = g_wa[g * 16 + c];
            float4 v = xs[c * 256 + t];
            sum += v.x + v.y + v.z + v.w;
            sq += v.x * v.x + v.y * v.y + v.z * v.z + v.w * v.w;
            p.x += w * v.x; p.y += w * v.y; p.z += w * v.z; p.w += w * v.w;
        }
        ((float4*)g_P)[bg * 256 + t] = p;

        float* s1 = smem;
        float* s2 = smem + 256;
        s1[t] = sum; s2[t] = sq;
        __syncthreads();
        for (int st = 128; st; st >>= 1) {
            if (t < st) { s1[t] += s1[t + st]; s2[t] += s2[t + st]; }
            __syncthreads();
        }
        if (t == 0) { g_sum[bg] = s1[0]; g_sq[bg] = s2[0]; }
    } else {
        // ---- k3 body ----
        int bx = blockIdx.x - 512;        // 0..127
        int mat = bx >> 6;                // 0 = k, 1 = v
        int ft = bx & 63;                 // f-tile of 16
        const float* W    = mat ? wv : wk;
        const float* bias = mat ? bv : bk;
        float* out        = mat ? g_v : g_k;

        float (*sw)[181] = (float (*)[181])smem;               // [16][181]
        float (*sc)[181] = (float (*)[181])(smem + 16 * 181);  // [16][181]
        int f0 = ft * 16;
        for (int i = t; i < 16 * 180; i += 256) {
            int r = i / 180, cc2 = i - r * 180;
            sw[r][cc2] = W[(size_t)(f0 + r) * TT + cc2];
            sc[r][cc2] = cond[r * TT + cc2];
        }
        __syncthreads();

        int fo = t & 15, bb = t >> 4;
        float acc = 0.f;
#pragma unroll 4
        for (int k = 0; k < TT; k++) acc += sw[fo][k] * sc[bb][k];
        out[bb * FF + f0 + fo] = acc + bias[f0 + fo];
    }
}

// ---------------- K4: finalize stats -> rs, per-batch offset d ----------------
// 1 block, 512 threads. warp w == batch b; lane == group g.
__global__ void k4() {
    int t = threadIdx.x;
    const float inv = 1.f / 16384.f;
    float mean = g_sum[t] * inv;
    float var = g_sq[t] * inv - mean * mean;
    float rs = rsqrtf(var + EPSF);
    g_rs[t] = rs;
    float contrib = mean * rs * g_wg[t & 31];
#pragma unroll
    for (int off = 16; off; off >>= 1)
        contrib += __shfl_down_sync(0xffffffffu, contrib, off);
    if ((t & 31) == 0) g_d[t >> 5] = g_const1 - contrib;
}

// ---------------- K5: S + softmax-weighted-average -> A[b,n] ----------------
// grid (128, 16), block 256 (8 warps; warp = one n).
// Logits are tiny (|l| < ~3 by construction: 0.02-scaled weights), so we skip
// the max-subtraction: exp never overflows and the ratio is exact.
__global__ void k5() {
    __shared__ float4 sk[256], sv[256];
    int b = blockIdx.y;
    int tid = threadIdx.x;
    sk[tid] = ((const float4*)(g_k + b * FF))[tid];
    sv[tid] = ((const float4*)(g_v + b * FF))[tid];
    __syncthreads();

    int w = tid >> 5, lane = tid & 31;
    int n = blockIdx.x * 8 + w;

    // S[b,n] = sum_g rs[b,g] * P[b,g,n] + d[b]   (lane-per-group)
    float ps = g_rs[b * 32 + lane] * g_P[((size_t)b * 32 + lane) * NN + n];
#pragma unroll
    for (int off = 16; off; off >>= 1) ps += __shfl_xor_sync(0xffffffffu, ps, off);
    float s = (ps + g_d[b]) * SCALE;

    float l = 0.f, acc = 0.f;
#pragma unroll
    for (int j = 0; j < 8; j++) {
        float4 k4v = sk[j * 32 + lane];
        float4 v4 = sv[j * 32 + lane];
        float e0 = __expf(s * k4v.x), e1 = __expf(s * k4v.y);
        float e2 = __expf(s * k4v.z), e3 = __expf(s * k4v.w);
        l += e0 + e1 + e2 + e3;
        acc += v4.x * e0 + v4.y * e1 + v4.z * e2 + v4.w * e3;
    }
#pragma unroll
    for (int off = 16; off; off >>= 1) {
        l += __shfl_xor_sync(0xffffffffu, l, off);
        acc += __shfl_xor_sync(0xffffffffu, acc, off);
    }
    if (lane == 0) g_A[b * NN + n] = acc / l;
}

// ---------------- K6: out = x + Wsum[c]*A[b,n] + bo[c] ----------------
// float4 over n. 8192 blocks x 256.
__global__ void k6(const float* __restrict__ x, const float* __restrict__ bo,
                   float* __restrict__ out) {
    size_t i = (size_t)blockIdx.x * 256 + threadIdx.x;  // float4 index
    int n4 = (int)(i & 255);
    int c = (int)((i >> 8) & 511);
    int b = (int)(i >> 17);
    float4 xv = ((const float4*)x)[i];
    float4 av = ((const float4*)g_A)[b * 256 + n4];
    float wv = g_Wsum[c];
    float bb = bo[c];
    float4 o;
    o.x = xv.x + wv * av.x + bb;
    o.y = xv.y + wv * av.y + bb;
    o.z = xv.z + wv * av.z + bb;
    o.w = xv.w + wv * av.w + bb;
    ((float4*)out)[i] = o;
}

extern "C" void kernel_launch(void* const* d_in, const int* in_sizes, int n_in,
                              void* d_out, int out_size) {
    const float* x     = (const float*)d_in[0];
    const float* cond  = (const float*)d_in[1];
    const float* gamma = (const float*)d_in[2];
    const float* beta  = (const float*)d_in[3];
    const float* wq    = (const float*)d_in[4];
    const float* bq    = (const float*)d_in[5];
    const float* wk    = (const float*)d_in[6];
    const float* bk    = (const float*)d_in[7];
    const float* wv    = (const float*)d_in[8];
    const float* bv    = (const float*)d_in[9];
    const float* wo    = (const float*)d_in[10];
    const float* bo    = (const float*)d_in[11];
    float* out = (float*)d_out;

    k1a<<<32, 512>>>(wq, wo);
    k1b<<<1, 512>>>(gamma, beta, bq);
    k23<<<640, 256>>>(x, cond, wk, bk, wv, bv);
    k4<<<1, 512>>>();
    k5<<<dim3(128, 16), 256>>>();
    k6<<<8192, 256>>>(x, bo, out);
}